// round 5
// baseline (speedup 1.0000x reference)
#include <cuda_runtime.h>
#include <math.h>
#include <stdint.h>

// ---------------------------------------------------------------------------
// Problem constants (fixed by the reference)
// ---------------------------------------------------------------------------
#define NMAX 20000          // N_MET == N_RXN == 20000
#define DHC  512            // H*C = 4*128
#define CDIM 128
#define EMAX 340000         // E (320000) + self loops (20000) for 'shared'

// ---------------------------------------------------------------------------
// Device scratch (static globals -- allocation inside kernel_launch is banned)
// ---------------------------------------------------------------------------
__device__ __align__(16) float g_xl[(size_t)NMAX * DHC];     // 40.96 MB
__device__ __align__(16) float g_xr[(size_t)NMAX * DHC];     // 40.96 MB
__device__ __align__(16) float g_outA[(size_t)NMAX * CDIM];  // out_sub
__device__ __align__(16) float g_outB[(size_t)NMAX * CDIM];  // out_shared
__device__ __align__(16) float g_outC[(size_t)NMAX * CDIM];  // out_prod
__device__ int g_cnt[NMAX];
__device__ int g_off[NMAX + 1];
__device__ int g_cur[NMAX];
__device__ int g_srcbuf[EMAX];

// ---------------------------------------------------------------------------
// GEMM: out[M,512] = X[M,128] @ W[128,512] + b   (out = g_xl or g_xr)
// Tile 128x64, K staged 2x64, 256 threads, 8x4 micro-tile per thread.
// ---------------------------------------------------------------------------
__global__ __launch_bounds__(256) void gemm_kernel(
    const float* __restrict__ X, const float* __restrict__ W,
    const float* __restrict__ bias, int destsel, int M)
{
    __shared__ float As[128 * 64];   // [row][k]   32 KB
    __shared__ float Bs[64 * 64];    // [k][n]     16 KB
    float* out = (destsel == 0) ? g_xl : g_xr;

    int tid = threadIdx.x;
    int m0 = blockIdx.x * 128;
    int n0 = blockIdx.y * 64;
    int tr = tid >> 4;      // 0..15 (row group of 8)
    int tc = tid & 15;      // 0..15 (col group of 4)

    float4 acc[8];
#pragma unroll
    for (int i = 0; i < 8; i++) acc[i] = make_float4(0.f, 0.f, 0.f, 0.f);

    for (int kc = 0; kc < 2; kc++) {
        // load A slab: 128 rows x 64 k  (2048 float4 / 256 thr = 8 each)
#pragma unroll
        for (int c = 0; c < 8; c++) {
            int li = tid + c * 256;
            int r = li >> 4, k4 = li & 15;
            float4 v = make_float4(0.f, 0.f, 0.f, 0.f);
            if (m0 + r < M)
                v = *(const float4*)(X + (size_t)(m0 + r) * 128 + kc * 64 + k4 * 4);
            *(float4*)(As + r * 64 + k4 * 4) = v;
        }
        // load B slab: 64 k x 64 n
#pragma unroll
        for (int c = 0; c < 4; c++) {
            int li = tid + c * 256;
            int k = li >> 4, c4 = li & 15;
            *(float4*)(Bs + k * 64 + c4 * 4) =
                *(const float4*)(W + (size_t)(kc * 64 + k) * 512 + n0 + c4 * 4);
        }
        __syncthreads();

#pragma unroll
        for (int k4 = 0; k4 < 16; k4++) {
            float4 b0 = *(float4*)(Bs + (k4 * 4 + 0) * 64 + tc * 4);
            float4 b1 = *(float4*)(Bs + (k4 * 4 + 1) * 64 + tc * 4);
            float4 b2 = *(float4*)(Bs + (k4 * 4 + 2) * 64 + tc * 4);
            float4 b3 = *(float4*)(Bs + (k4 * 4 + 3) * 64 + tc * 4);
#pragma unroll
            for (int i = 0; i < 8; i++) {
                float4 a = *(float4*)(As + (tr * 8 + i) * 64 + k4 * 4);
                acc[i].x += a.x * b0.x + a.y * b1.x + a.z * b2.x + a.w * b3.x;
                acc[i].y += a.x * b0.y + a.y * b1.y + a.z * b2.y + a.w * b3.y;
                acc[i].z += a.x * b0.z + a.y * b1.z + a.z * b2.z + a.w * b3.z;
                acc[i].w += a.x * b0.w + a.y * b1.w + a.z * b2.w + a.w * b3.w;
            }
        }
        __syncthreads();
    }

    float4 b4 = *(const float4*)(bias + n0 + tc * 4);
#pragma unroll
    for (int i = 0; i < 8; i++) {
        int m = m0 + tr * 8 + i;
        if (m < M) {
            float4 o;
            o.x = acc[i].x + b4.x; o.y = acc[i].y + b4.y;
            o.z = acc[i].z + b4.z; o.w = acc[i].w + b4.w;
            *(float4*)(out + (size_t)m * 512 + n0 + tc * 4) = o;
        }
    }
}

// ---------------------------------------------------------------------------
// CSR building
// ---------------------------------------------------------------------------
__global__ void zero_cnt_kernel(int n)
{
    int i = blockIdx.x * blockDim.x + threadIdx.x;
    if (i < n) g_cnt[i] = 0;
}

// ei layout: [0..E) = src, [E..2E) = dst.  extra self-loop edges appended.
__global__ void hist_kernel(const int* __restrict__ ei, int E, int n_extra, int n_dst)
{
    int idx = blockIdx.x * blockDim.x + threadIdx.x;
    if (idx >= E + n_extra) return;
    int d = (idx < E) ? ei[E + idx] : (idx - E);
    if (d >= 0 && d < n_dst) atomicAdd(&g_cnt[d], 1);
}

__global__ void scan_kernel(int n)
{
    __shared__ int sh[1024];
    __shared__ int s_carry;
    int tid = threadIdx.x;
    if (tid == 0) s_carry = 0;
    __syncthreads();
    for (int base = 0; base < n; base += 1024) {
        int i = base + tid;
        int v = (i < n) ? g_cnt[i] : 0;
        sh[tid] = v;
        __syncthreads();
        for (int off = 1; off < 1024; off <<= 1) {
            int t = (tid >= off) ? sh[tid - off] : 0;
            __syncthreads();
            sh[tid] += t;
            __syncthreads();
        }
        int incl = sh[tid];
        int excl = incl - v + s_carry;
        if (i < n) { g_off[i] = excl; g_cur[i] = excl; }
        __syncthreads();
        if (tid == 1023) s_carry += incl;
        __syncthreads();
    }
    if (tid == 0) g_off[n] = s_carry;
}

__global__ void scatter_kernel(const int* __restrict__ ei, int E, int n_extra, int n_dst)
{
    int idx = blockIdx.x * blockDim.x + threadIdx.x;
    if (idx >= E + n_extra) return;
    int s, d;
    if (idx < E) { s = ei[idx]; d = ei[E + idx]; }
    else         { s = d = idx - E; }
    if (d < 0 || d >= n_dst) return;
    int pos = atomicAdd(&g_cur[d], 1);
    if (pos >= 0 && pos < EMAX) g_srcbuf[pos] = s;
}

// ---------------------------------------------------------------------------
// GATv2 edge kernel: one warp per dst node, online softmax, no atomics.
// Lane l owns channels 4l..4l+3 of every head (float4 q == head q).
// out[dst][c] = (1/4) * sum_h acc[h][c]/den[h] + bias[c]
// ---------------------------------------------------------------------------
__global__ __launch_bounds__(256) void edge_kernel(
    const float* __restrict__ att, const float* __restrict__ bias,
    int outsel, int n_dst)
{
    int w = (blockIdx.x * blockDim.x + threadIdx.x) >> 5;
    int lane = threadIdx.x & 31;
    if (w >= n_dst) return;
    float* out = (outsel == 0) ? g_outA : (outsel == 1) ? g_outB : g_outC;

    const float4* xr4p = (const float4*)(g_xr + (size_t)w * DHC);
    const float4* att4p = (const float4*)att;

    float4 xr[4], at[4], acc[4];
#pragma unroll
    for (int q = 0; q < 4; q++) {
        xr[q] = xr4p[q * 32 + lane];
        at[q] = att4p[q * 32 + lane];
        acc[q] = make_float4(0.f, 0.f, 0.f, 0.f);
    }
    float m[4] = { -INFINITY, -INFINITY, -INFINITY, -INFINITY };
    float den[4] = { 0.f, 0.f, 0.f, 0.f };

    int j = g_off[w], end = g_off[w + 1];
    float4 nx[4];
    if (j < end) {
        const float4* p = (const float4*)(g_xl + (size_t)g_srcbuf[j] * DHC);
#pragma unroll
        for (int q = 0; q < 4; q++) nx[q] = p[q * 32 + lane];
    }
    while (j < end) {
        float4 xl[4];
#pragma unroll
        for (int q = 0; q < 4; q++) xl[q] = nx[q];
        j++;
        if (j < end) {   // prefetch next edge's xl row
            const float4* p = (const float4*)(g_xl + (size_t)g_srcbuf[j] * DHC);
#pragma unroll
            for (int q = 0; q < 4; q++) nx[q] = p[q * 32 + lane];
        }
        float s[4];
#pragma unroll
        for (int q = 0; q < 4; q++) {
            float ex = xl[q].x + xr[q].x; ex = fmaxf(ex, 0.2f * ex);
            float ey = xl[q].y + xr[q].y; ey = fmaxf(ey, 0.2f * ey);
            float ez = xl[q].z + xr[q].z; ez = fmaxf(ez, 0.2f * ez);
            float ew = xl[q].w + xr[q].w; ew = fmaxf(ew, 0.2f * ew);
            s[q] = ex * at[q].x + ey * at[q].y + ez * at[q].z + ew * at[q].w;
        }
#pragma unroll
        for (int o = 16; o; o >>= 1) {
#pragma unroll
            for (int q = 0; q < 4; q++)
                s[q] += __shfl_xor_sync(0xffffffffu, s[q], o);
        }
#pragma unroll
        for (int q = 0; q < 4; q++) {
            float mn = fmaxf(m[q], s[q]);
            float sc = __expf(m[q] - mn);
            float wg = __expf(s[q] - mn);
            den[q] = den[q] * sc + wg;
            acc[q].x = acc[q].x * sc + wg * xl[q].x;
            acc[q].y = acc[q].y * sc + wg * xl[q].y;
            acc[q].z = acc[q].z * sc + wg * xl[q].z;
            acc[q].w = acc[q].w * sc + wg * xl[q].w;
            m[q] = mn;
        }
    }
    float inv[4];
#pragma unroll
    for (int q = 0; q < 4; q++) inv[q] = (den[q] > 0.f) ? 1.f / den[q] : 0.f;
    float4 b4 = ((const float4*)bias)[lane];
    float4 o;
    o.x = (acc[0].x * inv[0] + acc[1].x * inv[1] + acc[2].x * inv[2] + acc[3].x * inv[3]) * 0.25f + b4.x;
    o.y = (acc[0].y * inv[0] + acc[1].y * inv[1] + acc[2].y * inv[2] + acc[3].y * inv[3]) * 0.25f + b4.y;
    o.z = (acc[0].z * inv[0] + acc[1].z * inv[1] + acc[2].z * inv[2] + acc[3].z * inv[3]) * 0.25f + b4.z;
    o.w = (acc[0].w * inv[0] + acc[1].w * inv[1] + acc[2].w * inv[2] + acc[3].w * inv[3]) * 0.25f + b4.w;
    ((float4*)(out + (size_t)w * CDIM))[lane] = o;
}

// ---------------------------------------------------------------------------
// JAX threefry2x32 core (matches jax._src.prng rotation/injection schedule)
// ---------------------------------------------------------------------------
__device__ __forceinline__ void threefry2x32(
    unsigned k0, unsigned k1, unsigned x0, unsigned x1,
    unsigned& o0, unsigned& o1)
{
    unsigned ks2 = k0 ^ k1 ^ 0x1BD11BDAu;
    x0 += k0; x1 += k1;
#define TFR(r) { x0 += x1; x1 = (x1 << r) | (x1 >> (32 - r)); x1 ^= x0; }
    TFR(13) TFR(15) TFR(26) TFR(6)  x0 += k1;  x1 += ks2 + 1u;
    TFR(17) TFR(29) TFR(16) TFR(24) x0 += ks2; x1 += k0 + 2u;
    TFR(13) TFR(15) TFR(26) TFR(6)  x0 += k0;  x1 += k1 + 3u;
    TFR(17) TFR(29) TFR(16) TFR(24) x0 += k1;  x1 += ks2 + 4u;
    TFR(13) TFR(15) TFR(26) TFR(6)  x0 += ks2; x1 += k0 + 5u;
#undef TFR
    o0 = x0; o1 = x1;
}

// ---------------------------------------------------------------------------
// Fused epilogue: combine relations -> ELU -> +residual -> LayerNorm -> MCdrop
// mode 0: rxn = 0.5*(outA+outB), residual x_rxn, key (0,101)
// mode 1: met = outC,            residual x_met, key (0,202)
// One warp per row (C=128 -> float4 per lane).
//
// Dropout matches jax_threefry_partitionable=True:
//   per element with 64-bit flat counter c (hi=0 here):
//     (o0,o1) = threefry2x32(key, hi32(c), lo32(c))
//     32-bit stream = o0 ^ o1            <-- partitionable bit_width<64 fold
//     u = bitcast((bits >> 9) | 0x3f800000) - 1 ;  keep iff u < 0.8
// ---------------------------------------------------------------------------
__global__ __launch_bounds__(256) void finalize_kernel(
    const float* __restrict__ xres, const float* __restrict__ gamma,
    const float* __restrict__ beta, float* __restrict__ out,
    int n, int mode, unsigned key1)
{
    int w = (blockIdx.x * blockDim.x + threadIdx.x) >> 5;
    int lane = threadIdx.x & 31;
    if (w >= n) return;

    const float4* A = (const float4*)((mode == 0) ? g_outA : g_outC);
    float4 v = A[(size_t)w * 32 + lane];
    if (mode == 0) {
        float4 b = ((const float4*)g_outB)[(size_t)w * 32 + lane];
        v.x = (v.x + b.x) * 0.5f; v.y = (v.y + b.y) * 0.5f;
        v.z = (v.z + b.z) * 0.5f; v.w = (v.w + b.w) * 0.5f;
    }
    // ELU
    v.x = (v.x > 0.f) ? v.x : expm1f(v.x);
    v.y = (v.y > 0.f) ? v.y : expm1f(v.y);
    v.z = (v.z > 0.f) ? v.z : expm1f(v.z);
    v.w = (v.w > 0.f) ? v.w : expm1f(v.w);
    // residual
    float4 r = ((const float4*)xres)[(size_t)w * 32 + lane];
    v.x += r.x; v.y += r.y; v.z += r.z; v.w += r.w;
    // LayerNorm over 128
    float sum = v.x + v.y + v.z + v.w;
#pragma unroll
    for (int o = 16; o; o >>= 1) sum += __shfl_xor_sync(0xffffffffu, sum, o);
    float mu = sum * (1.f / 128.f);
    float4 c;
    c.x = v.x - mu; c.y = v.y - mu; c.z = v.z - mu; c.w = v.w - mu;
    float sq = c.x * c.x + c.y * c.y + c.z * c.z + c.w * c.w;
#pragma unroll
    for (int o = 16; o; o >>= 1) sq += __shfl_xor_sync(0xffffffffu, sq, o);
    float rs = rsqrtf(sq * (1.f / 128.f) + 1e-5f);
    float4 g4 = ((const float4*)gamma)[lane];
    float4 b4 = ((const float4*)beta)[lane];
    float y[4];
    y[0] = c.x * rs * g4.x + b4.x;
    y[1] = c.y * rs * g4.y + b4.y;
    y[2] = c.z * rs * g4.z + b4.z;
    y[3] = c.w * rs * g4.w + b4.w;
    // MC dropout: partitionable threefry, counter = flat element index,
    // 32-bit stream = o0 ^ o1
    unsigned base = (unsigned)w * 128u + (unsigned)lane * 4u;
#pragma unroll
    for (int cc = 0; cc < 4; cc++) {
        unsigned flat = base + cc;
        unsigned o0, o1;
        threefry2x32(0u, key1, 0u, flat, o0, o1);
        unsigned bits = o0 ^ o1;
        float u = __uint_as_float((bits >> 9) | 0x3f800000u) - 1.f;
        y[cc] = (u < 0.8f) ? (y[cc] / 0.8f) : 0.f;
    }
    float4 o4; o4.x = y[0]; o4.y = y[1]; o4.z = y[2]; o4.w = y[3];
    ((float4*)(out + (size_t)w * CDIM))[lane] = o4;
}

// ---------------------------------------------------------------------------
// Host launcher
// Inputs (metadata order):
//  0 x_met  1 x_rxn  2 ei_sub  3 ei_prod  4 ei_shared
//  per relation {sub@5, prod@11, shared@17}: Wl, Wr, att, bl, br, bias
//  23 gamma_rxn 24 beta_rxn 25 gamma_met 26 beta_met
// Output: [rxn (n_rxn x 128), met (n_met x 128)] float32
// ---------------------------------------------------------------------------
extern "C" void kernel_launch(void* const* d_in, const int* in_sizes, int n_in,
                              void* d_out, int out_size)
{
    const float* x_met = (const float*)d_in[0];
    const float* x_rxn = (const float*)d_in[1];
    const int* ei_sub = (const int*)d_in[2];
    const int* ei_prod = (const int*)d_in[3];
    const int* ei_shared = (const int*)d_in[4];
    int n_met = in_sizes[0] / CDIM;
    int n_rxn = in_sizes[1] / CDIM;
    int E_sub = in_sizes[2] / 2;
    int E_prod = in_sizes[3] / 2;
    int E_shared = in_sizes[4] / 2;
    float* out = (float*)d_out;

    struct Rel {
        const float* xs; const float* xd; const int* ei;
        int E; int n_src; int n_dst; int base; int self_loops; int outsel;
    };
    Rel rels[3] = {
        { x_met, x_rxn, ei_sub,    E_sub,    n_met, n_rxn, 5,  0, 0 },
        { x_rxn, x_rxn, ei_shared, E_shared, n_rxn, n_rxn, 17, 1, 1 },
        { x_rxn, x_met, ei_prod,   E_prod,   n_rxn, n_met, 11, 0, 2 },
    };

    for (int rr = 0; rr < 3; rr++) {
        const Rel& R = rels[rr];
        const float* Wl = (const float*)d_in[R.base + 0];
        const float* Wr = (const float*)d_in[R.base + 1];
        const float* att = (const float*)d_in[R.base + 2];
        const float* bl = (const float*)d_in[R.base + 3];
        const float* br = (const float*)d_in[R.base + 4];
        const float* bias = (const float*)d_in[R.base + 5];

        dim3 gl((R.n_src + 127) / 128, 8);
        gemm_kernel<<<gl, 256>>>(R.xs, Wl, bl, 0, R.n_src);
        dim3 gr((R.n_dst + 127) / 128, 8);
        gemm_kernel<<<gr, 256>>>(R.xd, Wr, br, 1, R.n_dst);

        int n_extra = R.self_loops ? R.n_dst : 0;
        int tot = R.E + n_extra;
        zero_cnt_kernel<<<(R.n_dst + 255) / 256, 256>>>(R.n_dst);
        hist_kernel<<<(tot + 255) / 256, 256>>>(R.ei, R.E, n_extra, R.n_dst);
        scan_kernel<<<1, 1024>>>(R.n_dst);
        scatter_kernel<<<(tot + 255) / 256, 256>>>(R.ei, R.E, n_extra, R.n_dst);
        edge_kernel<<<(R.n_dst + 7) / 8, 256>>>(att, bias, R.outsel, R.n_dst);
    }

    // rxn output first, then met
    finalize_kernel<<<(n_rxn + 7) / 8, 256>>>(
        x_rxn, (const float*)d_in[23], (const float*)d_in[24],
        out, n_rxn, 0, 101u);
    finalize_kernel<<<(n_met + 7) / 8, 256>>>(
        x_met, (const float*)d_in[25], (const float*)d_in[26],
        out + (size_t)n_rxn * CDIM, n_met, 1, 202u);
}

// round 6
// speedup vs baseline: 1.0926x; 1.0926x over previous
#include <cuda_runtime.h>
#include <math.h>
#include <stdint.h>

// ---------------------------------------------------------------------------
// Problem constants (fixed by the reference)
// ---------------------------------------------------------------------------
#define NMAX 20000          // N_MET == N_RXN == 20000
#define DHC  512            // H*C = 4*128
#define CDIM 128
#define EMAX 340000         // E (320000) + self loops (20000) for 'shared'

// ---------------------------------------------------------------------------
// Device scratch
// ---------------------------------------------------------------------------
__device__ __align__(16) float g_xl[(size_t)NMAX * DHC];     // 40.96 MB
__device__ __align__(16) float g_xr[(size_t)NMAX * DHC];     // 40.96 MB
__device__ __align__(16) float g_outA[(size_t)NMAX * CDIM];  // out_sub
__device__ __align__(16) float g_outB[(size_t)NMAX * CDIM];  // out_shared
__device__ __align__(16) float g_outC[(size_t)NMAX * CDIM];  // out_prod
__device__ int g_cnt[NMAX];
__device__ int g_off[NMAX + 1];
__device__ int g_cur[NMAX];
__device__ int g_srcbuf[EMAX];

// ---------------------------------------------------------------------------
// tf32 helpers
// ---------------------------------------------------------------------------
__device__ __forceinline__ unsigned f2tf32(float x)
{
    unsigned r;
    asm("cvt.rna.tf32.f32 %0, %1;" : "=r"(r) : "f"(x));
    return r;
}

__device__ __forceinline__ void mma_tf32(float* c, const unsigned* a, const unsigned* b)
{
    asm volatile(
        "mma.sync.aligned.m16n8k8.row.col.f32.tf32.tf32.f32 "
        "{%0,%1,%2,%3}, {%4,%5,%6,%7}, {%8,%9}, {%0,%1,%2,%3};"
        : "+f"(c[0]), "+f"(c[1]), "+f"(c[2]), "+f"(c[3])
        : "r"(a[0]), "r"(a[1]), "r"(a[2]), "r"(a[3]), "r"(b[0]), "r"(b[1]));
}

// ---------------------------------------------------------------------------
// GEMM (tf32x3 on tensor cores): out[M,512] = X[M,128] @ W[128,512] + b
// Block tile 128x128, BK=16, 256 threads = 8 warps (4x2), warp tile 32x64.
// Each fp32 value is split hi/lo tf32; D += Ah*Bh + Ah*Bl + Al*Bh.
// Smem strides chosen conflict-free: A [m][k] stride 20, B [k][n] stride 136.
// ---------------------------------------------------------------------------
#define GBM 128
#define GBN 128
#define GBK 16
#define ASTR 20
#define BSTR 136

__global__ __launch_bounds__(256) void gemm_tf32_kernel(
    const float* __restrict__ X, const float* __restrict__ W,
    const float* __restrict__ bias, int destsel, int M)
{
    __shared__ unsigned Ah[GBM * ASTR], Al[GBM * ASTR];
    __shared__ unsigned Bh[GBK * BSTR], Bl[GBK * BSTR];

    float* out = (destsel == 0) ? g_xl : g_xr;
    int tid = threadIdx.x;
    int m0 = blockIdx.x * GBM;
    int n0 = blockIdx.y * GBN;
    int w = tid >> 5, lane = tid & 31;
    int wm = (w & 3) * 32;        // warp row offset in tile
    int wn = (w >> 2) * 64;       // warp col offset in tile
    int g = lane >> 2, tg = lane & 3;

    float c[2][8][4];
#pragma unroll
    for (int mt = 0; mt < 2; mt++)
#pragma unroll
        for (int nt = 0; nt < 8; nt++)
#pragma unroll
            for (int i = 0; i < 4; i++) c[mt][nt][i] = 0.f;

    for (int kc = 0; kc < 8; kc++) {
        // load A slab: 128 rows x 16 k = 512 float4, 2 per thread
#pragma unroll
        for (int i = 0; i < 2; i++) {
            int idx = tid + i * 256;
            int r = idx >> 2, k4 = idx & 3;
            float4 v = make_float4(0.f, 0.f, 0.f, 0.f);
            if (m0 + r < M)
                v = *(const float4*)(X + (size_t)(m0 + r) * 128 + kc * 16 + k4 * 4);
            unsigned h0 = f2tf32(v.x), h1 = f2tf32(v.y), h2 = f2tf32(v.z), h3 = f2tf32(v.w);
            int base = r * ASTR + k4 * 4;
            Ah[base + 0] = h0; Ah[base + 1] = h1; Ah[base + 2] = h2; Ah[base + 3] = h3;
            Al[base + 0] = f2tf32(v.x - __uint_as_float(h0));
            Al[base + 1] = f2tf32(v.y - __uint_as_float(h1));
            Al[base + 2] = f2tf32(v.z - __uint_as_float(h2));
            Al[base + 3] = f2tf32(v.w - __uint_as_float(h3));
        }
        // load B slab: 16 k x 128 n = 512 float4, 2 per thread
#pragma unroll
        for (int i = 0; i < 2; i++) {
            int idx = tid + i * 256;
            int r = idx >> 5, n4 = idx & 31;
            float4 v = *(const float4*)(W + (size_t)(kc * 16 + r) * 512 + n0 + n4 * 4);
            unsigned h0 = f2tf32(v.x), h1 = f2tf32(v.y), h2 = f2tf32(v.z), h3 = f2tf32(v.w);
            int base = r * BSTR + n4 * 4;
            Bh[base + 0] = h0; Bh[base + 1] = h1; Bh[base + 2] = h2; Bh[base + 3] = h3;
            Bl[base + 0] = f2tf32(v.x - __uint_as_float(h0));
            Bl[base + 1] = f2tf32(v.y - __uint_as_float(h1));
            Bl[base + 2] = f2tf32(v.z - __uint_as_float(h2));
            Bl[base + 3] = f2tf32(v.w - __uint_as_float(h3));
        }
        __syncthreads();

#pragma unroll
        for (int ks = 0; ks < 2; ks++) {
            int k0 = ks * 8;
            unsigned ah[2][4], al[2][4];
#pragma unroll
            for (int mt = 0; mt < 2; mt++) {
                int row = wm + mt * 16;
                ah[mt][0] = Ah[(row + g)     * ASTR + k0 + tg];
                ah[mt][1] = Ah[(row + g + 8) * ASTR + k0 + tg];
                ah[mt][2] = Ah[(row + g)     * ASTR + k0 + tg + 4];
                ah[mt][3] = Ah[(row + g + 8) * ASTR + k0 + tg + 4];
                al[mt][0] = Al[(row + g)     * ASTR + k0 + tg];
                al[mt][1] = Al[(row + g + 8) * ASTR + k0 + tg];
                al[mt][2] = Al[(row + g)     * ASTR + k0 + tg + 4];
                al[mt][3] = Al[(row + g + 8) * ASTR + k0 + tg + 4];
            }
#pragma unroll
            for (int nt = 0; nt < 8; nt++) {
                int col = wn + nt * 8 + g;
                unsigned bh[2], bl[2];
                bh[0] = Bh[(k0 + tg)     * BSTR + col];
                bh[1] = Bh[(k0 + tg + 4) * BSTR + col];
                bl[0] = Bl[(k0 + tg)     * BSTR + col];
                bl[1] = Bl[(k0 + tg + 4) * BSTR + col];
#pragma unroll
                for (int mt = 0; mt < 2; mt++) {
                    mma_tf32(c[mt][nt], ah[mt], bh);
                    mma_tf32(c[mt][nt], ah[mt], bl);
                    mma_tf32(c[mt][nt], al[mt], bh);
                }
            }
        }
        __syncthreads();
    }

    // epilogue: bias add + store
#pragma unroll
    for (int mt = 0; mt < 2; mt++) {
#pragma unroll
        for (int nt = 0; nt < 8; nt++) {
            int col = n0 + wn + nt * 8 + tg * 2;
            float b0 = __ldg(bias + col);
            float b1 = __ldg(bias + col + 1);
            int row0 = m0 + wm + mt * 16 + g;
            if (row0 < M) {
                float2 v0 = make_float2(c[mt][nt][0] + b0, c[mt][nt][1] + b1);
                *(float2*)(out + (size_t)row0 * 512 + col) = v0;
            }
            int row1 = row0 + 8;
            if (row1 < M) {
                float2 v1 = make_float2(c[mt][nt][2] + b0, c[mt][nt][3] + b1);
                *(float2*)(out + (size_t)row1 * 512 + col) = v1;
            }
        }
    }
}

// ---------------------------------------------------------------------------
// CSR building
// ---------------------------------------------------------------------------
__global__ void zero_cnt_kernel(int n)
{
    int i = blockIdx.x * blockDim.x + threadIdx.x;
    if (i < n) g_cnt[i] = 0;
}

__global__ void hist_kernel(const int* __restrict__ ei, int E, int n_extra, int n_dst)
{
    int idx = blockIdx.x * blockDim.x + threadIdx.x;
    if (idx >= E + n_extra) return;
    int d = (idx < E) ? ei[E + idx] : (idx - E);
    if (d >= 0 && d < n_dst) atomicAdd(&g_cnt[d], 1);
}

__global__ void scan_kernel(int n)
{
    __shared__ int sh[1024];
    __shared__ int s_carry;
    int tid = threadIdx.x;
    if (tid == 0) s_carry = 0;
    __syncthreads();
    for (int base = 0; base < n; base += 1024) {
        int i = base + tid;
        int v = (i < n) ? g_cnt[i] : 0;
        sh[tid] = v;
        __syncthreads();
        for (int off = 1; off < 1024; off <<= 1) {
            int t = (tid >= off) ? sh[tid - off] : 0;
            __syncthreads();
            sh[tid] += t;
            __syncthreads();
        }
        int incl = sh[tid];
        int excl = incl - v + s_carry;
        if (i < n) { g_off[i] = excl; g_cur[i] = excl; }
        __syncthreads();
        if (tid == 1023) s_carry += incl;
        __syncthreads();
    }
    if (tid == 0) g_off[n] = s_carry;
}

__global__ void scatter_kernel(const int* __restrict__ ei, int E, int n_extra, int n_dst)
{
    int idx = blockIdx.x * blockDim.x + threadIdx.x;
    if (idx >= E + n_extra) return;
    int s, d;
    if (idx < E) { s = ei[idx]; d = ei[E + idx]; }
    else         { s = d = idx - E; }
    if (d < 0 || d >= n_dst) return;
    int pos = atomicAdd(&g_cur[d], 1);
    if (pos >= 0 && pos < EMAX) g_srcbuf[pos] = s;
}

// ---------------------------------------------------------------------------
// GATv2 edge kernel: one warp per dst node, online softmax, no atomics.
// ---------------------------------------------------------------------------
__global__ __launch_bounds__(256) void edge_kernel(
    const float* __restrict__ att, const float* __restrict__ bias,
    int outsel, int n_dst)
{
    int w = (blockIdx.x * blockDim.x + threadIdx.x) >> 5;
    int lane = threadIdx.x & 31;
    if (w >= n_dst) return;
    float* out = (outsel == 0) ? g_outA : (outsel == 1) ? g_outB : g_outC;

    const float4* xr4p = (const float4*)(g_xr + (size_t)w * DHC);
    const float4* att4p = (const float4*)att;

    float4 xr[4], at[4], acc[4];
#pragma unroll
    for (int q = 0; q < 4; q++) {
        xr[q] = xr4p[q * 32 + lane];
        at[q] = att4p[q * 32 + lane];
        acc[q] = make_float4(0.f, 0.f, 0.f, 0.f);
    }
    float m[4] = { -INFINITY, -INFINITY, -INFINITY, -INFINITY };
    float den[4] = { 0.f, 0.f, 0.f, 0.f };

    int j = g_off[w], end = g_off[w + 1];
    float4 nx[4];
    if (j < end) {
        const float4* p = (const float4*)(g_xl + (size_t)g_srcbuf[j] * DHC);
#pragma unroll
        for (int q = 0; q < 4; q++) nx[q] = p[q * 32 + lane];
    }
    while (j < end) {
        float4 xl[4];
#pragma unroll
        for (int q = 0; q < 4; q++) xl[q] = nx[q];
        j++;
        if (j < end) {
            const float4* p = (const float4*)(g_xl + (size_t)g_srcbuf[j] * DHC);
#pragma unroll
            for (int q = 0; q < 4; q++) nx[q] = p[q * 32 + lane];
        }
        float s[4];
#pragma unroll
        for (int q = 0; q < 4; q++) {
            float ex = xl[q].x + xr[q].x; ex = fmaxf(ex, 0.2f * ex);
            float ey = xl[q].y + xr[q].y; ey = fmaxf(ey, 0.2f * ey);
            float ez = xl[q].z + xr[q].z; ez = fmaxf(ez, 0.2f * ez);
            float ew = xl[q].w + xr[q].w; ew = fmaxf(ew, 0.2f * ew);
            s[q] = ex * at[q].x + ey * at[q].y + ez * at[q].z + ew * at[q].w;
        }
#pragma unroll
        for (int o = 16; o; o >>= 1) {
#pragma unroll
            for (int q = 0; q < 4; q++)
                s[q] += __shfl_xor_sync(0xffffffffu, s[q], o);
        }
#pragma unroll
        for (int q = 0; q < 4; q++) {
            float mn = fmaxf(m[q], s[q]);
            float sc = __expf(m[q] - mn);
            float wg = __expf(s[q] - mn);
            den[q] = den[q] * sc + wg;
            acc[q].x = acc[q].x * sc + wg * xl[q].x;
            acc[q].y = acc[q].y * sc + wg * xl[q].y;
            acc[q].z = acc[q].z * sc + wg * xl[q].z;
            acc[q].w = acc[q].w * sc + wg * xl[q].w;
            m[q] = mn;
        }
    }
    float inv[4];
#pragma unroll
    for (int q = 0; q < 4; q++) inv[q] = (den[q] > 0.f) ? 1.f / den[q] : 0.f;
    float4 b4 = ((const float4*)bias)[lane];
    float4 o;
    o.x = (acc[0].x * inv[0] + acc[1].x * inv[1] + acc[2].x * inv[2] + acc[3].x * inv[3]) * 0.25f + b4.x;
    o.y = (acc[0].y * inv[0] + acc[1].y * inv[1] + acc[2].y * inv[2] + acc[3].y * inv[3]) * 0.25f + b4.y;
    o.z = (acc[0].z * inv[0] + acc[1].z * inv[1] + acc[2].z * inv[2] + acc[3].z * inv[3]) * 0.25f + b4.z;
    o.w = (acc[0].w * inv[0] + acc[1].w * inv[1] + acc[2].w * inv[2] + acc[3].w * inv[3]) * 0.25f + b4.w;
    ((float4*)(out + (size_t)w * CDIM))[lane] = o;
}

// ---------------------------------------------------------------------------
// JAX threefry2x32 core
// ---------------------------------------------------------------------------
__device__ __forceinline__ void threefry2x32(
    unsigned k0, unsigned k1, unsigned x0, unsigned x1,
    unsigned& o0, unsigned& o1)
{
    unsigned ks2 = k0 ^ k1 ^ 0x1BD11BDAu;
    x0 += k0; x1 += k1;
#define TFR(r) { x0 += x1; x1 = (x1 << r) | (x1 >> (32 - r)); x1 ^= x0; }
    TFR(13) TFR(15) TFR(26) TFR(6)  x0 += k1;  x1 += ks2 + 1u;
    TFR(17) TFR(29) TFR(16) TFR(24) x0 += ks2; x1 += k0 + 2u;
    TFR(13) TFR(15) TFR(26) TFR(6)  x0 += k0;  x1 += k1 + 3u;
    TFR(17) TFR(29) TFR(16) TFR(24) x0 += k1;  x1 += ks2 + 4u;
    TFR(13) TFR(15) TFR(26) TFR(6)  x0 += ks2; x1 += k0 + 5u;
#undef TFR
    o0 = x0; o1 = x1;
}

// ---------------------------------------------------------------------------
// Fused epilogue (partitionable threefry: bits = o0 ^ o1)
// ---------------------------------------------------------------------------
__global__ __launch_bounds__(256) void finalize_kernel(
    const float* __restrict__ xres, const float* __restrict__ gamma,
    const float* __restrict__ beta, float* __restrict__ out,
    int n, int mode, unsigned key1)
{
    int w = (blockIdx.x * blockDim.x + threadIdx.x) >> 5;
    int lane = threadIdx.x & 31;
    if (w >= n) return;

    const float4* A = (const float4*)((mode == 0) ? g_outA : g_outC);
    float4 v = A[(size_t)w * 32 + lane];
    if (mode == 0) {
        float4 b = ((const float4*)g_outB)[(size_t)w * 32 + lane];
        v.x = (v.x + b.x) * 0.5f; v.y = (v.y + b.y) * 0.5f;
        v.z = (v.z + b.z) * 0.5f; v.w = (v.w + b.w) * 0.5f;
    }
    v.x = (v.x > 0.f) ? v.x : expm1f(v.x);
    v.y = (v.y > 0.f) ? v.y : expm1f(v.y);
    v.z = (v.z > 0.f) ? v.z : expm1f(v.z);
    v.w = (v.w > 0.f) ? v.w : expm1f(v.w);
    float4 r = ((const float4*)xres)[(size_t)w * 32 + lane];
    v.x += r.x; v.y += r.y; v.z += r.z; v.w += r.w;
    float sum = v.x + v.y + v.z + v.w;
#pragma unroll
    for (int o = 16; o; o >>= 1) sum += __shfl_xor_sync(0xffffffffu, sum, o);
    float mu = sum * (1.f / 128.f);
    float4 c;
    c.x = v.x - mu; c.y = v.y - mu; c.z = v.z - mu; c.w = v.w - mu;
    float sq = c.x * c.x + c.y * c.y + c.z * c.z + c.w * c.w;
#pragma unroll
    for (int o = 16; o; o >>= 1) sq += __shfl_xor_sync(0xffffffffu, sq, o);
    float rs = rsqrtf(sq * (1.f / 128.f) + 1e-5f);
    float4 g4 = ((const float4*)gamma)[lane];
    float4 b4 = ((const float4*)beta)[lane];
    float y[4];
    y[0] = c.x * rs * g4.x + b4.x;
    y[1] = c.y * rs * g4.y + b4.y;
    y[2] = c.z * rs * g4.z + b4.z;
    y[3] = c.w * rs * g4.w + b4.w;
    unsigned base = (unsigned)w * 128u + (unsigned)lane * 4u;
#pragma unroll
    for (int cc = 0; cc < 4; cc++) {
        unsigned flat = base + cc;
        unsigned o0, o1;
        threefry2x32(0u, key1, 0u, flat, o0, o1);
        unsigned bits = o0 ^ o1;
        float u = __uint_as_float((bits >> 9) | 0x3f800000u) - 1.f;
        y[cc] = (u < 0.8f) ? (y[cc] / 0.8f) : 0.f;
    }
    float4 o4; o4.x = y[0]; o4.y = y[1]; o4.z = y[2]; o4.w = y[3];
    ((float4*)(out + (size_t)w * CDIM))[lane] = o4;
}

// ---------------------------------------------------------------------------
// Host launcher
// ---------------------------------------------------------------------------
extern "C" void kernel_launch(void* const* d_in, const int* in_sizes, int n_in,
                              void* d_out, int out_size)
{
    const float* x_met = (const float*)d_in[0];
    const float* x_rxn = (const float*)d_in[1];
    const int* ei_sub = (const int*)d_in[2];
    const int* ei_prod = (const int*)d_in[3];
    const int* ei_shared = (const int*)d_in[4];
    int n_met = in_sizes[0] / CDIM;
    int n_rxn = in_sizes[1] / CDIM;
    int E_sub = in_sizes[2] / 2;
    int E_prod = in_sizes[3] / 2;
    int E_shared = in_sizes[4] / 2;
    float* out = (float*)d_out;

    struct Rel {
        const float* xs; const float* xd; const int* ei;
        int E; int n_src; int n_dst; int base; int self_loops; int outsel;
    };
    Rel rels[3] = {
        { x_met, x_rxn, ei_sub,    E_sub,    n_met, n_rxn, 5,  0, 0 },
        { x_rxn, x_rxn, ei_shared, E_shared, n_rxn, n_rxn, 17, 1, 1 },
        { x_rxn, x_met, ei_prod,   E_prod,   n_rxn, n_met, 11, 0, 2 },
    };

    for (int rr = 0; rr < 3; rr++) {
        const Rel& R = rels[rr];
        const float* Wl = (const float*)d_in[R.base + 0];
        const float* Wr = (const float*)d_in[R.base + 1];
        const float* att = (const float*)d_in[R.base + 2];
        const float* bl = (const float*)d_in[R.base + 3];
        const float* br = (const float*)d_in[R.base + 4];
        const float* bias = (const float*)d_in[R.base + 5];

        dim3 gl((R.n_src + GBM - 1) / GBM, 512 / GBN);
        gemm_tf32_kernel<<<gl, 256>>>(R.xs, Wl, bl, 0, R.n_src);
        dim3 gr((R.n_dst + GBM - 1) / GBM, 512 / GBN);
        gemm_tf32_kernel<<<gr, 256>>>(R.xd, Wr, br, 1, R.n_dst);

        int n_extra = R.self_loops ? R.n_dst : 0;
        int tot = R.E + n_extra;
        zero_cnt_kernel<<<(R.n_dst + 255) / 256, 256>>>(R.n_dst);
        hist_kernel<<<(tot + 255) / 256, 256>>>(R.ei, R.E, n_extra, R.n_dst);
        scan_kernel<<<1, 1024>>>(R.n_dst);
        scatter_kernel<<<(tot + 255) / 256, 256>>>(R.ei, R.E, n_extra, R.n_dst);
        edge_kernel<<<(R.n_dst + 7) / 8, 256>>>(att, bias, R.outsel, R.n_dst);
    }

    finalize_kernel<<<(n_rxn + 7) / 8, 256>>>(
        x_rxn, (const float*)d_in[23], (const float*)d_in[24],
        out, n_rxn, 0, 101u);
    finalize_kernel<<<(n_met + 7) / 8, 256>>>(
        x_met, (const float*)d_in[25], (const float*)d_in[26],
        out + (size_t)n_rxn * CDIM, n_met, 1, 202u);
}

// round 9
// speedup vs baseline: 1.2374x; 1.1325x over previous
#include <cuda_runtime.h>
#include <math.h>
#include <stdint.h>

// ---------------------------------------------------------------------------
// Problem constants
// ---------------------------------------------------------------------------
#define NMAX 20000
#define DHC  512            // H*C
#define CDIM 128
#define EMAXR 340000        // max edges per relation incl self loops

// ---------------------------------------------------------------------------
// Device scratch — single xl/xr buffers (≈85 MB total, matches passing runs)
// ---------------------------------------------------------------------------
__device__ __align__(16) float g_xl[(size_t)NMAX * DHC];    // 40.96 MB
__device__ __align__(16) float g_xr[(size_t)NMAX * DHC];    // 40.96 MB
__device__ __align__(16) float g_outA[(size_t)NMAX * CDIM];
__device__ __align__(16) float g_outB[(size_t)NMAX * CDIM];
__device__ __align__(16) float g_outC[(size_t)NMAX * CDIM];
__device__ int g_cnt3[3][NMAX];
__device__ int g_off3[3][NMAX + 1];
__device__ int g_cur3[3][NMAX];
__device__ int g_srcbuf3[3][EMAXR];

struct CsrArgs {
    const int* ei[3];
    int E[3];
    int n_extra[3];
    int n_dst[3];
};

// ---------------------------------------------------------------------------
// tf32 helpers
// ---------------------------------------------------------------------------
__device__ __forceinline__ unsigned f2tf32(float x)
{
    unsigned r;
    asm("cvt.rna.tf32.f32 %0, %1;" : "=r"(r) : "f"(x));
    return r;
}

__device__ __forceinline__ void mma_tf32(float* c, const unsigned* a, const unsigned* b)
{
    asm volatile(
        "mma.sync.aligned.m16n8k8.row.col.f32.tf32.tf32.f32 "
        "{%0,%1,%2,%3}, {%4,%5,%6,%7}, {%8,%9}, {%0,%1,%2,%3};"
        : "+f"(c[0]), "+f"(c[1]), "+f"(c[2]), "+f"(c[3])
        : "r"(a[0]), "r"(a[1]), "r"(a[2]), "r"(a[3]), "r"(b[0]), "r"(b[1]));
}

// ---------------------------------------------------------------------------
// Paired GEMM (tf32x3): both GEMMs of one relation in ONE launch.
// blockIdx.z = 0: g_xl = Xs @ Wl + bl ; z = 1: g_xr = Xd @ Wr + br.
// Block tile 128x128, BK=16, 256 thr, 8 warps (4x2), warp tile 32x64.
// ---------------------------------------------------------------------------
#define GBM 128
#define ASTR 20
#define BSTR 136

__global__ __launch_bounds__(256) void gemm_pair_kernel(
    const float* __restrict__ Xl, const float* __restrict__ Wl,
    const float* __restrict__ bl, int Ml,
    const float* __restrict__ Xr, const float* __restrict__ Wr,
    const float* __restrict__ br, int Mr)
{
    __shared__ unsigned Ah[GBM * ASTR], Al[GBM * ASTR];
    __shared__ unsigned Bh[16 * BSTR], Bl[16 * BSTR];

    int z = blockIdx.z;
    const float* __restrict__ X = z ? Xr : Xl;
    const float* __restrict__ W = z ? Wr : Wl;
    const float* __restrict__ bias = z ? br : bl;
    int M = z ? Mr : Ml;
    float* out = z ? g_xr : g_xl;

    int tid = threadIdx.x;
    int m0 = blockIdx.x * GBM;
    if (m0 >= M) return;
    int n0 = blockIdx.y * 128;
    int w = tid >> 5, lane = tid & 31;
    int wm = (w & 3) * 32;
    int wn = (w >> 2) * 64;
    int g = lane >> 2, tg = lane & 3;

    float c[2][8][4];
#pragma unroll
    for (int mt = 0; mt < 2; mt++)
#pragma unroll
        for (int nt = 0; nt < 8; nt++)
#pragma unroll
            for (int i = 0; i < 4; i++) c[mt][nt][i] = 0.f;

    for (int kc = 0; kc < 8; kc++) {
#pragma unroll
        for (int i = 0; i < 2; i++) {
            int idx = tid + i * 256;
            int r = idx >> 2, k4 = idx & 3;
            float4 v = make_float4(0.f, 0.f, 0.f, 0.f);
            if (m0 + r < M)
                v = *(const float4*)(X + (size_t)(m0 + r) * 128 + kc * 16 + k4 * 4);
            unsigned h0 = f2tf32(v.x), h1 = f2tf32(v.y), h2 = f2tf32(v.z), h3 = f2tf32(v.w);
            int base = r * ASTR + k4 * 4;
            Ah[base + 0] = h0; Ah[base + 1] = h1; Ah[base + 2] = h2; Ah[base + 3] = h3;
            Al[base + 0] = f2tf32(v.x - __uint_as_float(h0));
            Al[base + 1] = f2tf32(v.y - __uint_as_float(h1));
            Al[base + 2] = f2tf32(v.z - __uint_as_float(h2));
            Al[base + 3] = f2tf32(v.w - __uint_as_float(h3));
        }
#pragma unroll
        for (int i = 0; i < 2; i++) {
            int idx = tid + i * 256;
            int r = idx >> 5, n4 = idx & 31;
            float4 v = *(const float4*)(W + (size_t)(kc * 16 + r) * 512 + n0 + n4 * 4);
            unsigned h0 = f2tf32(v.x), h1 = f2tf32(v.y), h2 = f2tf32(v.z), h3 = f2tf32(v.w);
            int base = r * BSTR + n4 * 4;
            Bh[base + 0] = h0; Bh[base + 1] = h1; Bh[base + 2] = h2; Bh[base + 3] = h3;
            Bl[base + 0] = f2tf32(v.x - __uint_as_float(h0));
            Bl[base + 1] = f2tf32(v.y - __uint_as_float(h1));
            Bl[base + 2] = f2tf32(v.z - __uint_as_float(h2));
            Bl[base + 3] = f2tf32(v.w - __uint_as_float(h3));
        }
        __syncthreads();

#pragma unroll
        for (int ks = 0; ks < 2; ks++) {
            int k0 = ks * 8;
            unsigned ah[2][4], al[2][4];
#pragma unroll
            for (int mt = 0; mt < 2; mt++) {
                int row = wm + mt * 16;
                ah[mt][0] = Ah[(row + g)     * ASTR + k0 + tg];
                ah[mt][1] = Ah[(row + g + 8) * ASTR + k0 + tg];
                ah[mt][2] = Ah[(row + g)     * ASTR + k0 + tg + 4];
                ah[mt][3] = Ah[(row + g + 8) * ASTR + k0 + tg + 4];
                al[mt][0] = Al[(row + g)     * ASTR + k0 + tg];
                al[mt][1] = Al[(row + g + 8) * ASTR + k0 + tg];
                al[mt][2] = Al[(row + g)     * ASTR + k0 + tg + 4];
                al[mt][3] = Al[(row + g + 8) * ASTR + k0 + tg + 4];
            }
#pragma unroll
            for (int nt = 0; nt < 8; nt++) {
                int col = wn + nt * 8 + g;
                unsigned bh[2], bl2[2];
                bh[0] = Bh[(k0 + tg)     * BSTR + col];
                bh[1] = Bh[(k0 + tg + 4) * BSTR + col];
                bl2[0] = Bl[(k0 + tg)     * BSTR + col];
                bl2[1] = Bl[(k0 + tg + 4) * BSTR + col];
#pragma unroll
                for (int mt = 0; mt < 2; mt++) {
                    mma_tf32(c[mt][nt], ah[mt], bh);
                    mma_tf32(c[mt][nt], ah[mt], bl2);
                    mma_tf32(c[mt][nt], al[mt], bh);
                }
            }
        }
        __syncthreads();
    }

#pragma unroll
    for (int mt = 0; mt < 2; mt++) {
#pragma unroll
        for (int nt = 0; nt < 8; nt++) {
            int col = n0 + wn + nt * 8 + tg * 2;
            float b0 = __ldg(bias + col);
            float b1 = __ldg(bias + col + 1);
            int row0 = m0 + wm + mt * 16 + g;
            if (row0 < M) {
                float2 v0 = make_float2(c[mt][nt][0] + b0, c[mt][nt][1] + b1);
                *(float2*)(out + (size_t)row0 * 512 + col) = v0;
            }
            int row1 = row0 + 8;
            if (row1 < M) {
                float2 v1 = make_float2(c[mt][nt][2] + b0, c[mt][nt][3] + b1);
                *(float2*)(out + (size_t)row1 * 512 + col) = v1;
            }
        }
    }
}

// ---------------------------------------------------------------------------
// Fused CSR build (all relations)
// ---------------------------------------------------------------------------
__global__ void zero_all_kernel(int n0, int n1, int n2)
{
    int i = blockIdx.x * blockDim.x + threadIdx.x;
    if (i < n0) g_cnt3[0][i] = 0;
    if (i < n1) g_cnt3[1][i] = 0;
    if (i < n2) g_cnt3[2][i] = 0;
}

__global__ void hist_all_kernel(CsrArgs a)
{
    int rel = blockIdx.y;
    int idx = blockIdx.x * blockDim.x + threadIdx.x;
    int E = a.E[rel];
    if (idx >= E + a.n_extra[rel]) return;
    int d = (idx < E) ? a.ei[rel][E + idx] : (idx - E);
    if (d >= 0 && d < a.n_dst[rel]) atomicAdd(&g_cnt3[rel][d], 1);
}

__global__ void scan_all_kernel(int nd0, int nd1, int nd2)
{
    __shared__ int sh[1024];
    __shared__ int s_carry;
    int rel = blockIdx.x;
    int n = (rel == 0) ? nd0 : (rel == 1) ? nd1 : nd2;
    int tid = threadIdx.x;
    if (tid == 0) s_carry = 0;
    __syncthreads();
    for (int base = 0; base < n; base += 1024) {
        int i = base + tid;
        int v = (i < n) ? g_cnt3[rel][i] : 0;
        sh[tid] = v;
        __syncthreads();
        for (int off = 1; off < 1024; off <<= 1) {
            int t = (tid >= off) ? sh[tid - off] : 0;
            __syncthreads();
            sh[tid] += t;
            __syncthreads();
        }
        int incl = sh[tid];
        int excl = incl - v + s_carry;
        if (i < n) { g_off3[rel][i] = excl; g_cur3[rel][i] = excl; }
        __syncthreads();
        if (tid == 1023) s_carry += incl;
        __syncthreads();
    }
    if (tid == 0) g_off3[rel][n] = s_carry;
}

__global__ void scatter_all_kernel(CsrArgs a)
{
    int rel = blockIdx.y;
    int idx = blockIdx.x * blockDim.x + threadIdx.x;
    int E = a.E[rel];
    if (idx >= E + a.n_extra[rel]) return;
    int s, d;
    if (idx < E) { s = a.ei[rel][idx]; d = a.ei[rel][E + idx]; }
    else         { s = d = idx - E; }
    if (d < 0 || d >= a.n_dst[rel]) return;
    int pos = atomicAdd(&g_cur3[rel][d], 1);
    if (pos >= 0 && pos < EMAXR) g_srcbuf3[rel][pos] = s;
}

// ---------------------------------------------------------------------------
// GATv2 edge kernel: one warp per dst node, online softmax, no atomics.
// Reads g_xl/g_xr (current relation), CSR by rel; out by rel.
// ---------------------------------------------------------------------------
__global__ __launch_bounds__(256) void edge_kernel(
    const float* __restrict__ att, const float* __restrict__ bias,
    int rel, int n_dst)
{
    int w = (blockIdx.x * blockDim.x + threadIdx.x) >> 5;
    int lane = threadIdx.x & 31;
    if (w >= n_dst) return;
    float* out = (rel == 0) ? g_outA : (rel == 1) ? g_outB : g_outC;
    const int* srcbuf = g_srcbuf3[rel];

    const float4* xr4p = (const float4*)(g_xr + (size_t)w * DHC);
    const float4* att4p = (const float4*)att;

    float4 xr[4], at[4], acc[4];
#pragma unroll
    for (int q = 0; q < 4; q++) {
        xr[q] = xr4p[q * 32 + lane];
        at[q] = att4p[q * 32 + lane];
        acc[q] = make_float4(0.f, 0.f, 0.f, 0.f);
    }
    float m[4] = { -INFINITY, -INFINITY, -INFINITY, -INFINITY };
    float den[4] = { 0.f, 0.f, 0.f, 0.f };

    int j = g_off3[rel][w], end = g_off3[rel][w + 1];
    float4 nx[4];
    if (j < end) {
        const float4* p = (const float4*)(g_xl + (size_t)srcbuf[j] * DHC);
#pragma unroll
        for (int q = 0; q < 4; q++) nx[q] = p[q * 32 + lane];
    }
    while (j < end) {
        float4 xl[4];
#pragma unroll
        for (int q = 0; q < 4; q++) xl[q] = nx[q];
        j++;
        if (j < end) {
            const float4* p = (const float4*)(g_xl + (size_t)srcbuf[j] * DHC);
#pragma unroll
            for (int q = 0; q < 4; q++) nx[q] = p[q * 32 + lane];
        }
        float s[4];
#pragma unroll
        for (int q = 0; q < 4; q++) {
            float ex = xl[q].x + xr[q].x; ex = fmaxf(ex, 0.2f * ex);
            float ey = xl[q].y + xr[q].y; ey = fmaxf(ey, 0.2f * ey);
            float ez = xl[q].z + xr[q].z; ez = fmaxf(ez, 0.2f * ez);
            float ew = xl[q].w + xr[q].w; ew = fmaxf(ew, 0.2f * ew);
            s[q] = ex * at[q].x + ey * at[q].y + ez * at[q].z + ew * at[q].w;
        }
#pragma unroll
        for (int o = 16; o; o >>= 1) {
#pragma unroll
            for (int q = 0; q < 4; q++)
                s[q] += __shfl_xor_sync(0xffffffffu, s[q], o);
        }
#pragma unroll
        for (int q = 0; q < 4; q++) {
            float mn = fmaxf(m[q], s[q]);
            float sc = __expf(m[q] - mn);
            float wg = __expf(s[q] - mn);
            den[q] = den[q] * sc + wg;
            acc[q].x = acc[q].x * sc + wg * xl[q].x;
            acc[q].y = acc[q].y * sc + wg * xl[q].y;
            acc[q].z = acc[q].z * sc + wg * xl[q].z;
            acc[q].w = acc[q].w * sc + wg * xl[q].w;
            m[q] = mn;
        }
    }
    float inv[4];
#pragma unroll
    for (int q = 0; q < 4; q++) inv[q] = (den[q] > 0.f) ? 1.f / den[q] : 0.f;
    float4 b4 = ((const float4*)bias)[lane];
    float4 o;
    o.x = (acc[0].x * inv[0] + acc[1].x * inv[1] + acc[2].x * inv[2] + acc[3].x * inv[3]) * 0.25f + b4.x;
    o.y = (acc[0].y * inv[0] + acc[1].y * inv[1] + acc[2].y * inv[2] + acc[3].y * inv[3]) * 0.25f + b4.y;
    o.z = (acc[0].z * inv[0] + acc[1].z * inv[1] + acc[2].z * inv[2] + acc[3].z * inv[3]) * 0.25f + b4.z;
    o.w = (acc[0].w * inv[0] + acc[1].w * inv[1] + acc[2].w * inv[2] + acc[3].w * inv[3]) * 0.25f + b4.w;
    ((float4*)(out + (size_t)w * CDIM))[lane] = o;
}

// ---------------------------------------------------------------------------
// JAX threefry2x32 core
// ---------------------------------------------------------------------------
__device__ __forceinline__ void threefry2x32(
    unsigned k0, unsigned k1, unsigned x0, unsigned x1,
    unsigned& o0, unsigned& o1)
{
    unsigned ks2 = k0 ^ k1 ^ 0x1BD11BDAu;
    x0 += k0; x1 += k1;
#define TFR(r) { x0 += x1; x1 = (x1 << r) | (x1 >> (32 - r)); x1 ^= x0; }
    TFR(13) TFR(15) TFR(26) TFR(6)  x0 += k1;  x1 += ks2 + 1u;
    TFR(17) TFR(29) TFR(16) TFR(24) x0 += ks2; x1 += k0 + 2u;
    TFR(13) TFR(15) TFR(26) TFR(6)  x0 += k0;  x1 += k1 + 3u;
    TFR(17) TFR(29) TFR(16) TFR(24) x0 += k1;  x1 += ks2 + 4u;
    TFR(13) TFR(15) TFR(26) TFR(6)  x0 += ks2; x1 += k0 + 5u;
#undef TFR
    o0 = x0; o1 = x1;
}

// ---------------------------------------------------------------------------
// Fused epilogue for BOTH node types in one launch.
// ---------------------------------------------------------------------------
__global__ __launch_bounds__(256) void finalize_all_kernel(
    const float* __restrict__ x_rxn, const float* __restrict__ x_met,
    const float* __restrict__ gr, const float* __restrict__ br,
    const float* __restrict__ gm, const float* __restrict__ bm,
    float* __restrict__ out, int n_rxn, int n_met)
{
    int wg = (blockIdx.x * blockDim.x + threadIdx.x) >> 5;
    int lane = threadIdx.x & 31;
    if (wg >= n_rxn + n_met) return;

    int mode = (wg < n_rxn) ? 0 : 1;
    int w = (mode == 0) ? wg : wg - n_rxn;
    const float* xres = (mode == 0) ? x_rxn : x_met;
    const float* gamma = (mode == 0) ? gr : gm;
    const float* beta = (mode == 0) ? br : bm;
    unsigned key1 = (mode == 0) ? 101u : 202u;
    float* o_base = (mode == 0) ? out : out + (size_t)n_rxn * CDIM;

    const float4* A = (const float4*)((mode == 0) ? g_outA : g_outC);
    float4 v = A[(size_t)w * 32 + lane];
    if (mode == 0) {
        float4 b = ((const float4*)g_outB)[(size_t)w * 32 + lane];
        v.x = (v.x + b.x) * 0.5f; v.y = (v.y + b.y) * 0.5f;
        v.z = (v.z + b.z) * 0.5f; v.w = (v.w + b.w) * 0.5f;
    }
    v.x = (v.x > 0.f) ? v.x : expm1f(v.x);
    v.y = (v.y > 0.f) ? v.y : expm1f(v.y);
    v.z = (v.z > 0.f) ? v.z : expm1f(v.z);
    v.w = (v.w > 0.f) ? v.w : expm1f(v.w);
    float4 r = ((const float4*)xres)[(size_t)w * 32 + lane];
    v.x += r.x; v.y += r.y; v.z += r.z; v.w += r.w;
    float sum = v.x + v.y + v.z + v.w;
#pragma unroll
    for (int o = 16; o; o >>= 1) sum += __shfl_xor_sync(0xffffffffu, sum, o);
    float mu = sum * (1.f / 128.f);
    float4 c;
    c.x = v.x - mu; c.y = v.y - mu; c.z = v.z - mu; c.w = v.w - mu;
    float sq = c.x * c.x + c.y * c.y + c.z * c.z + c.w * c.w;
#pragma unroll
    for (int o = 16; o; o >>= 1) sq += __shfl_xor_sync(0xffffffffu, sq, o);
    float rs = rsqrtf(sq * (1.f / 128.f) + 1e-5f);
    float4 g4 = ((const float4*)gamma)[lane];
    float4 b4 = ((const float4*)beta)[lane];
    float y[4];
    y[0] = c.x * rs * g4.x + b4.x;
    y[1] = c.y * rs * g4.y + b4.y;
    y[2] = c.z * rs * g4.z + b4.z;
    y[3] = c.w * rs * g4.w + b4.w;
    unsigned base = (unsigned)w * 128u + (unsigned)lane * 4u;
#pragma unroll
    for (int cc = 0; cc < 4; cc++) {
        unsigned flat = base + cc;
        unsigned o0, o1;
        threefry2x32(0u, key1, 0u, flat, o0, o1);
        unsigned bits = o0 ^ o1;
        float u = __uint_as_float((bits >> 9) | 0x3f800000u) - 1.f;
        y[cc] = (u < 0.8f) ? (y[cc] / 0.8f) : 0.f;
    }
    float4 o4; o4.x = y[0]; o4.y = y[1]; o4.z = y[2]; o4.w = y[3];
    ((float4*)(o_base + (size_t)w * CDIM))[lane] = o4;
}

// ---------------------------------------------------------------------------
// Host launcher — 11 launches total
// ---------------------------------------------------------------------------
extern "C" void kernel_launch(void* const* d_in, const int* in_sizes, int n_in,
                              void* d_out, int out_size)
{
    const float* x_met = (const float*)d_in[0];
    const float* x_rxn = (const float*)d_in[1];
    const int* ei_sub = (const int*)d_in[2];
    const int* ei_prod = (const int*)d_in[3];
    const int* ei_shared = (const int*)d_in[4];
    int n_met = in_sizes[0] / CDIM;
    int n_rxn = in_sizes[1] / CDIM;
    int E_sub = in_sizes[2] / 2;
    int E_prod = in_sizes[3] / 2;
    int E_shared = in_sizes[4] / 2;
    float* out = (float*)d_out;

    // relation order: 0=sub(met->rxn), 1=shared(rxn->rxn,+loops), 2=prod(rxn->met)
    const float* xs[3] = { x_met, x_rxn, x_rxn };
    const float* xd[3] = { x_rxn, x_rxn, x_met };
    int n_src[3] = { n_met, n_rxn, n_rxn };
    int n_dst[3] = { n_rxn, n_rxn, n_met };
    int baseidx[3] = { 5, 17, 11 };

    CsrArgs ca;
    ca.ei[0] = ei_sub;    ca.E[0] = E_sub;    ca.n_extra[0] = 0;     ca.n_dst[0] = n_rxn;
    ca.ei[1] = ei_shared; ca.E[1] = E_shared; ca.n_extra[1] = n_rxn; ca.n_dst[1] = n_rxn;
    ca.ei[2] = ei_prod;   ca.E[2] = E_prod;   ca.n_extra[2] = 0;     ca.n_dst[2] = n_met;

    int nmax_nodes = (n_rxn > n_met) ? n_rxn : n_met;
    int tot_max = 0;
    for (int r = 0; r < 3; r++) {
        int t = ca.E[r] + ca.n_extra[r];
        if (t > tot_max) tot_max = t;
    }

    // 1-4: fused CSR build
    zero_all_kernel<<<(nmax_nodes + 255) / 256, 256>>>(ca.n_dst[0], ca.n_dst[1], ca.n_dst[2]);
    {
        dim3 g((tot_max + 255) / 256, 3);
        hist_all_kernel<<<g, 256>>>(ca);
    }
    scan_all_kernel<<<3, 1024>>>(ca.n_dst[0], ca.n_dst[1], ca.n_dst[2]);
    {
        dim3 g((tot_max + 255) / 256, 3);
        scatter_all_kernel<<<g, 256>>>(ca);
    }

    // 5-10: per relation: paired GEMM launch + edge kernel
    for (int r = 0; r < 3; r++) {
        const float* Wl = (const float*)d_in[baseidx[r] + 0];
        const float* Wr = (const float*)d_in[baseidx[r] + 1];
        const float* att = (const float*)d_in[baseidx[r] + 2];
        const float* bl = (const float*)d_in[baseidx[r] + 3];
        const float* br = (const float*)d_in[baseidx[r] + 4];
        const float* bias = (const float*)d_in[baseidx[r] + 5];

        int mmax = (n_src[r] > n_dst[r]) ? n_src[r] : n_dst[r];
        dim3 g((mmax + GBM - 1) / GBM, 4, 2);
        gemm_pair_kernel<<<g, 256>>>(xs[r], Wl, bl, n_src[r],
                                     xd[r], Wr, br, n_dst[r]);
        edge_kernel<<<(n_dst[r] + 7) / 8, 256>>>(att, bias, r, n_dst[r]);
    }

    // 11: fused finalize
    {
        int tw = n_rxn + n_met;
        finalize_all_kernel<<<(tw + 7) / 8, 256>>>(
            x_rxn, x_met,
            (const float*)d_in[23], (const float*)d_in[24],
            (const float*)d_in[25], (const float*)d_in[26],
            out, n_rxn, n_met);
    }
}

// round 10
// speedup vs baseline: 1.3574x; 1.0970x over previous
#include <cuda_runtime.h>
#include <cuda_bf16.h>
#include <math.h>
#include <stdint.h>

// ---------------------------------------------------------------------------
// Problem constants
// ---------------------------------------------------------------------------
#define NMAX 20000
#define DHC  512            // H*C
#define CDIM 128
#define EMAXR 340000        // max edges per relation incl self loops

// ---------------------------------------------------------------------------
// Device scratch — single xl/xr buffers (~85 MB, matches passing runs)
// ---------------------------------------------------------------------------
__device__ __align__(16) float g_xl[(size_t)NMAX * DHC];
__device__ __align__(16) float g_xr[(size_t)NMAX * DHC];
__device__ __align__(16) float g_outA[(size_t)NMAX * CDIM];
__device__ __align__(16) float g_outB[(size_t)NMAX * CDIM];
__device__ __align__(16) float g_outC[(size_t)NMAX * CDIM];
__device__ int g_cnt3[3][NMAX];
__device__ int g_off3[3][NMAX + 1];
__device__ int g_cur3[3][NMAX];
__device__ int g_srcbuf3[3][EMAXR];

struct CsrArgs {
    const int* ei[3];
    int E[3];
    int n_extra[3];
    int n_dst[3];
};

// ---------------------------------------------------------------------------
// bf16 split helpers: x = hi + lo (each bf16), pack two k-consecutive values
// into one u32 (low half = even k).
// ---------------------------------------------------------------------------
__device__ __forceinline__ void bsplit2(float x, float y, unsigned& h, unsigned& l)
{
    unsigned short hx = __bfloat16_as_ushort(__float2bfloat16_rn(x));
    unsigned short hy = __bfloat16_as_ushort(__float2bfloat16_rn(y));
    float rx = x - __bfloat162float(__ushort_as_bfloat16(hx));
    float ry = y - __bfloat162float(__ushort_as_bfloat16(hy));
    unsigned short lx = __bfloat16_as_ushort(__float2bfloat16_rn(rx));
    unsigned short ly = __bfloat16_as_ushort(__float2bfloat16_rn(ry));
    h = ((unsigned)hy << 16) | (unsigned)hx;
    l = ((unsigned)ly << 16) | (unsigned)lx;
}

__device__ __forceinline__ void mma_bf16(float* c, const unsigned* a, const unsigned* b)
{
    asm volatile(
        "mma.sync.aligned.m16n8k16.row.col.f32.bf16.bf16.f32 "
        "{%0,%1,%2,%3}, {%4,%5,%6,%7}, {%8,%9}, {%0,%1,%2,%3};"
        : "+f"(c[0]), "+f"(c[1]), "+f"(c[2]), "+f"(c[3])
        : "r"(a[0]), "r"(a[1]), "r"(a[2]), "r"(a[3]), "r"(b[0]), "r"(b[1]));
}

// ---------------------------------------------------------------------------
// Paired GEMM (bf16x3): both GEMMs of one relation in ONE launch.
// blockIdx.z = 0: g_xl = Xs @ Wl + bl ; z = 1: g_xr = Xd @ Wr + br.
// Block tile 128x128, BK=32 (2 x k16 mma-steps per stage), 256 thr,
// 8 warps (4x2), warp tile 32x64. D += Ah*Bh + Ah*Bl + Al*Bh.
// Smem: A [row][kp] stride 20 (u32 kp = k-pair), B [col][kp] stride 20.
// ---------------------------------------------------------------------------
#define GBM 128
#define PSTR 20

__global__ __launch_bounds__(256) void gemm_pair_kernel(
    const float* __restrict__ Xl, const float* __restrict__ Wl,
    const float* __restrict__ bl, int Ml,
    const float* __restrict__ Xr, const float* __restrict__ Wr,
    const float* __restrict__ br, int Mr)
{
    __shared__ unsigned AhP[128 * PSTR], AlP[128 * PSTR];   // 10 KB each
    __shared__ unsigned BhP[128 * PSTR], BlP[128 * PSTR];   // 10 KB each

    int z = blockIdx.z;
    const float* __restrict__ X = z ? Xr : Xl;
    const float* __restrict__ W = z ? Wr : Wl;
    const float* __restrict__ bias = z ? br : bl;
    int M = z ? Mr : Ml;
    float* out = z ? g_xr : g_xl;

    int tid = threadIdx.x;
    int m0 = blockIdx.x * GBM;
    if (m0 >= M) return;
    int n0 = blockIdx.y * 128;
    int w = tid >> 5, lane = tid & 31;
    int wm = (w & 3) * 32;
    int wn = (w >> 2) * 64;
    int g = lane >> 2, tg = lane & 3;

    float c[2][8][4];
#pragma unroll
    for (int mt = 0; mt < 2; mt++)
#pragma unroll
        for (int nt = 0; nt < 8; nt++)
#pragma unroll
            for (int i = 0; i < 4; i++) c[mt][nt][i] = 0.f;

    for (int kc = 0; kc < 4; kc++) {
        // A slab: 128 rows x 32 k = 1024 float4; 4 per thread.
#pragma unroll
        for (int i = 0; i < 4; i++) {
            int idx = tid + i * 256;
            int r = idx >> 3, f4 = idx & 7;
            float4 v = make_float4(0.f, 0.f, 0.f, 0.f);
            if (m0 + r < M)
                v = *(const float4*)(X + (size_t)(m0 + r) * 128 + kc * 32 + f4 * 4);
            unsigned h0, l0, h1, l1;
            bsplit2(v.x, v.y, h0, l0);
            bsplit2(v.z, v.w, h1, l1);
            int base = r * PSTR + f4 * 2;
            AhP[base] = h0; AhP[base + 1] = h1;
            AlP[base] = l0; AlP[base + 1] = l1;
        }
        // B slab: 32 k x 128 n -> B[col][kp]; kp varies within warp for
        // conflict-free stores (addr = 20*(4*c4+j) + kp).
#pragma unroll
        for (int i = 0; i < 2; i++) {
            int idx = tid + i * 256;
            int kp = idx & 15, c4 = idx >> 4;   // c4 in 0..31
            int krow = kc * 32 + kp * 2;
            float4 v0 = *(const float4*)(W + (size_t)krow * 512 + n0 + c4 * 4);
            float4 v1 = *(const float4*)(W + (size_t)(krow + 1) * 512 + n0 + c4 * 4);
            unsigned h, l;
            bsplit2(v0.x, v1.x, h, l);
            BhP[(c4 * 4 + 0) * PSTR + kp] = h; BlP[(c4 * 4 + 0) * PSTR + kp] = l;
            bsplit2(v0.y, v1.y, h, l);
            BhP[(c4 * 4 + 1) * PSTR + kp] = h; BlP[(c4 * 4 + 1) * PSTR + kp] = l;
            bsplit2(v0.z, v1.z, h, l);
            BhP[(c4 * 4 + 2) * PSTR + kp] = h; BlP[(c4 * 4 + 2) * PSTR + kp] = l;
            bsplit2(v0.w, v1.w, h, l);
            BhP[(c4 * 4 + 3) * PSTR + kp] = h; BlP[(c4 * 4 + 3) * PSTR + kp] = l;
        }
        __syncthreads();

#pragma unroll
        for (int ks = 0; ks < 2; ks++) {
            int kp0 = ks * 8;
            unsigned ah[2][4], al[2][4];
#pragma unroll
            for (int mt = 0; mt < 2; mt++) {
                int row = wm + mt * 16;
                ah[mt][0] = AhP[(row + g)     * PSTR + kp0 + tg];
                ah[mt][1] = AhP[(row + g + 8) * PSTR + kp0 + tg];
                ah[mt][2] = AhP[(row + g)     * PSTR + kp0 + tg + 4];
                ah[mt][3] = AhP[(row + g + 8) * PSTR + kp0 + tg + 4];
                al[mt][0] = AlP[(row + g)     * PSTR + kp0 + tg];
                al[mt][1] = AlP[(row + g + 8) * PSTR + kp0 + tg];
                al[mt][2] = AlP[(row + g)     * PSTR + kp0 + tg + 4];
                al[mt][3] = AlP[(row + g + 8) * PSTR + kp0 + tg + 4];
            }
#pragma unroll
            for (int nt = 0; nt < 8; nt++) {
                int col = wn + nt * 8 + g;
                unsigned bh[2], bl2[2];
                bh[0]  = BhP[col * PSTR + kp0 + tg];
                bh[1]  = BhP[col * PSTR + kp0 + tg + 4];
                bl2[0] = BlP[col * PSTR + kp0 + tg];
                bl2[1] = BlP[col * PSTR + kp0 + tg + 4];
#pragma unroll
                for (int mt = 0; mt < 2; mt++) {
                    mma_bf16(c[mt][nt], ah[mt], bh);
                    mma_bf16(c[mt][nt], ah[mt], bl2);
                    mma_bf16(c[mt][nt], al[mt], bh);
                }
            }
        }
        __syncthreads();
    }

#pragma unroll
    for (int mt = 0; mt < 2; mt++) {
#pragma unroll
        for (int nt = 0; nt < 8; nt++) {
            int col = n0 + wn + nt * 8 + tg * 2;
            float b0 = __ldg(bias + col);
            float b1 = __ldg(bias + col + 1);
            int row0 = m0 + wm + mt * 16 + g;
            if (row0 < M) {
                float2 v0 = make_float2(c[mt][nt][0] + b0, c[mt][nt][1] + b1);
                *(float2*)(out + (size_t)row0 * 512 + col) = v0;
            }
            int row1 = row0 + 8;
            if (row1 < M) {
                float2 v1 = make_float2(c[mt][nt][2] + b0, c[mt][nt][3] + b1);
                *(float2*)(out + (size_t)row1 * 512 + col) = v1;
            }
        }
    }
}

// ---------------------------------------------------------------------------
// Fused CSR build (all relations)
// ---------------------------------------------------------------------------
__global__ void zero_all_kernel(int n0, int n1, int n2)
{
    int i = blockIdx.x * blockDim.x + threadIdx.x;
    if (i < n0) g_cnt3[0][i] = 0;
    if (i < n1) g_cnt3[1][i] = 0;
    if (i < n2) g_cnt3[2][i] = 0;
}

__global__ void hist_all_kernel(CsrArgs a)
{
    int rel = blockIdx.y;
    int idx = blockIdx.x * blockDim.x + threadIdx.x;
    int E = a.E[rel];
    if (idx >= E + a.n_extra[rel]) return;
    int d = (idx < E) ? a.ei[rel][E + idx] : (idx - E);
    if (d >= 0 && d < a.n_dst[rel]) atomicAdd(&g_cnt3[rel][d], 1);
}

__global__ void scan_all_kernel(int nd0, int nd1, int nd2)
{
    __shared__ int sh[1024];
    __shared__ int s_carry;
    int rel = blockIdx.x;
    int n = (rel == 0) ? nd0 : (rel == 1) ? nd1 : nd2;
    int tid = threadIdx.x;
    if (tid == 0) s_carry = 0;
    __syncthreads();
    for (int base = 0; base < n; base += 1024) {
        int i = base + tid;
        int v = (i < n) ? g_cnt3[rel][i] : 0;
        sh[tid] = v;
        __syncthreads();
        for (int off = 1; off < 1024; off <<= 1) {
            int t = (tid >= off) ? sh[tid - off] : 0;
            __syncthreads();
            sh[tid] += t;
            __syncthreads();
        }
        int incl = sh[tid];
        int excl = incl - v + s_carry;
        if (i < n) { g_off3[rel][i] = excl; g_cur3[rel][i] = excl; }
        __syncthreads();
        if (tid == 1023) s_carry += incl;
        __syncthreads();
    }
    if (tid == 0) g_off3[rel][n] = s_carry;
}

__global__ void scatter_all_kernel(CsrArgs a)
{
    int rel = blockIdx.y;
    int idx = blockIdx.x * blockDim.x + threadIdx.x;
    int E = a.E[rel];
    if (idx >= E + a.n_extra[rel]) return;
    int s, d;
    if (idx < E) { s = a.ei[rel][idx]; d = a.ei[rel][E + idx]; }
    else         { s = d = idx - E; }
    if (d < 0 || d >= a.n_dst[rel]) return;
    int pos = atomicAdd(&g_cur3[rel][d], 1);
    if (pos >= 0 && pos < EMAXR) g_srcbuf3[rel][pos] = s;
}

// ---------------------------------------------------------------------------
// GATv2 edge kernel: one warp per dst node, online softmax, no atomics.
// ---------------------------------------------------------------------------
__global__ __launch_bounds__(256) void edge_kernel(
    const float* __restrict__ att, const float* __restrict__ bias,
    int rel, int n_dst)
{
    int w = (blockIdx.x * blockDim.x + threadIdx.x) >> 5;
    int lane = threadIdx.x & 31;
    if (w >= n_dst) return;
    float* out = (rel == 0) ? g_outA : (rel == 1) ? g_outB : g_outC;
    const int* srcbuf = g_srcbuf3[rel];

    const float4* xr4p = (const float4*)(g_xr + (size_t)w * DHC);
    const float4* att4p = (const float4*)att;

    float4 xr[4], at[4], acc[4];
#pragma unroll
    for (int q = 0; q < 4; q++) {
        xr[q] = xr4p[q * 32 + lane];
        at[q] = att4p[q * 32 + lane];
        acc[q] = make_float4(0.f, 0.f, 0.f, 0.f);
    }
    float m[4] = { -INFINITY, -INFINITY, -INFINITY, -INFINITY };
    float den[4] = { 0.f, 0.f, 0.f, 0.f };

    int j = g_off3[rel][w], end = g_off3[rel][w + 1];
    float4 nx[4];
    if (j < end) {
        const float4* p = (const float4*)(g_xl + (size_t)srcbuf[j] * DHC);
#pragma unroll
        for (int q = 0; q < 4; q++) nx[q] = p[q * 32 + lane];
    }
    while (j < end) {
        float4 xl[4];
#pragma unroll
        for (int q = 0; q < 4; q++) xl[q] = nx[q];
        j++;
        if (j < end) {
            const float4* p = (const float4*)(g_xl + (size_t)srcbuf[j] * DHC);
#pragma unroll
            for (int q = 0; q < 4; q++) nx[q] = p[q * 32 + lane];
        }
        float s[4];
#pragma unroll
        for (int q = 0; q < 4; q++) {
            float ex = xl[q].x + xr[q].x; ex = fmaxf(ex, 0.2f * ex);
            float ey = xl[q].y + xr[q].y; ey = fmaxf(ey, 0.2f * ey);
            float ez = xl[q].z + xr[q].z; ez = fmaxf(ez, 0.2f * ez);
            float ew = xl[q].w + xr[q].w; ew = fmaxf(ew, 0.2f * ew);
            s[q] = ex * at[q].x + ey * at[q].y + ez * at[q].z + ew * at[q].w;
        }
#pragma unroll
        for (int o = 16; o; o >>= 1) {
#pragma unroll
            for (int q = 0; q < 4; q++)
                s[q] += __shfl_xor_sync(0xffffffffu, s[q], o);
        }
#pragma unroll
        for (int q = 0; q < 4; q++) {
            float mn = fmaxf(m[q], s[q]);
            float sc = __expf(m[q] - mn);
            float wg = __expf(s[q] - mn);
            den[q] = den[q] * sc + wg;
            acc[q].x = acc[q].x * sc + wg * xl[q].x;
            acc[q].y = acc[q].y * sc + wg * xl[q].y;
            acc[q].z = acc[q].z * sc + wg * xl[q].z;
            acc[q].w = acc[q].w * sc + wg * xl[q].w;
            m[q] = mn;
        }
    }
    float inv[4];
#pragma unroll
    for (int q = 0; q < 4; q++) inv[q] = (den[q] > 0.f) ? 1.f / den[q] : 0.f;
    float4 b4 = ((const float4*)bias)[lane];
    float4 o;
    o.x = (acc[0].x * inv[0] + acc[1].x * inv[1] + acc[2].x * inv[2] + acc[3].x * inv[3]) * 0.25f + b4.x;
    o.y = (acc[0].y * inv[0] + acc[1].y * inv[1] + acc[2].y * inv[2] + acc[3].y * inv[3]) * 0.25f + b4.y;
    o.z = (acc[0].z * inv[0] + acc[1].z * inv[1] + acc[2].z * inv[2] + acc[3].z * inv[3]) * 0.25f + b4.z;
    o.w = (acc[0].w * inv[0] + acc[1].w * inv[1] + acc[2].w * inv[2] + acc[3].w * inv[3]) * 0.25f + b4.w;
    ((float4*)(out + (size_t)w * CDIM))[lane] = o;
}

// ---------------------------------------------------------------------------
// JAX threefry2x32 core
// ---------------------------------------------------------------------------
__device__ __forceinline__ void threefry2x32(
    unsigned k0, unsigned k1, unsigned x0, unsigned x1,
    unsigned& o0, unsigned& o1)
{
    unsigned ks2 = k0 ^ k1 ^ 0x1BD11BDAu;
    x0 += k0; x1 += k1;
#define TFR(r) { x0 += x1; x1 = (x1 << r) | (x1 >> (32 - r)); x1 ^= x0; }
    TFR(13) TFR(15) TFR(26) TFR(6)  x0 += k1;  x1 += ks2 + 1u;
    TFR(17) TFR(29) TFR(16) TFR(24) x0 += ks2; x1 += k0 + 2u;
    TFR(13) TFR(15) TFR(26) TFR(6)  x0 += k0;  x1 += k1 + 3u;
    TFR(17) TFR(29) TFR(16) TFR(24) x0 += k1;  x1 += ks2 + 4u;
    TFR(13) TFR(15) TFR(26) TFR(6)  x0 += ks2; x1 += k0 + 5u;
#undef TFR
    o0 = x0; o1 = x1;
}

// ---------------------------------------------------------------------------
// Fused epilogue for BOTH node types in one launch.
// ---------------------------------------------------------------------------
__global__ __launch_bounds__(256) void finalize_all_kernel(
    const float* __restrict__ x_rxn, const float* __restrict__ x_met,
    const float* __restrict__ gr, const float* __restrict__ br,
    const float* __restrict__ gm, const float* __restrict__ bm,
    float* __restrict__ out, int n_rxn, int n_met)
{
    int wg = (blockIdx.x * blockDim.x + threadIdx.x) >> 5;
    int lane = threadIdx.x & 31;
    if (wg >= n_rxn + n_met) return;

    int mode = (wg < n_rxn) ? 0 : 1;
    int w = (mode == 0) ? wg : wg - n_rxn;
    const float* xres = (mode == 0) ? x_rxn : x_met;
    const float* gamma = (mode == 0) ? gr : gm;
    const float* beta = (mode == 0) ? br : bm;
    unsigned key1 = (mode == 0) ? 101u : 202u;
    float* o_base = (mode == 0) ? out : out + (size_t)n_rxn * CDIM;

    const float4* A = (const float4*)((mode == 0) ? g_outA : g_outC);
    float4 v = A[(size_t)w * 32 + lane];
    if (mode == 0) {
        float4 b = ((const float4*)g_outB)[(size_t)w * 32 + lane];
        v.x = (v.x + b.x) * 0.5f; v.y = (v.y + b.y) * 0.5f;
        v.z = (v.z + b.z) * 0.5f; v.w = (v.w + b.w) * 0.5f;
    }
    v.x = (v.x > 0.f) ? v.x : expm1f(v.x);
    v.y = (v.y > 0.f) ? v.y : expm1f(v.y);
    v.z = (v.z > 0.f) ? v.z : expm1f(v.z);
    v.w = (v.w > 0.f) ? v.w : expm1f(v.w);
    float4 r = ((const float4*)xres)[(size_t)w * 32 + lane];
    v.x += r.x; v.y += r.y; v.z += r.z; v.w += r.w;
    float sum = v.x + v.y + v.z + v.w;
#pragma unroll
    for (int o = 16; o; o >>= 1) sum += __shfl_xor_sync(0xffffffffu, sum, o);
    float mu = sum * (1.f / 128.f);
    float4 c;
    c.x = v.x - mu; c.y = v.y - mu; c.z = v.z - mu; c.w = v.w - mu;
    float sq = c.x * c.x + c.y * c.y + c.z * c.z + c.w * c.w;
#pragma unroll
    for (int o = 16; o; o >>= 1) sq += __shfl_xor_sync(0xffffffffu, sq, o);
    float rs = rsqrtf(sq * (1.f / 128.f) + 1e-5f);
    float4 g4 = ((const float4*)gamma)[lane];
    float4 b4 = ((const float4*)beta)[lane];
    float y[4];
    y[0] = c.x * rs * g4.x + b4.x;
    y[1] = c.y * rs * g4.y + b4.y;
    y[2] = c.z * rs * g4.z + b4.z;
    y[3] = c.w * rs * g4.w + b4.w;
    unsigned base = (unsigned)w * 128u + (unsigned)lane * 4u;
#pragma unroll
    for (int cc = 0; cc < 4; cc++) {
        unsigned flat = base + cc;
        unsigned o0, o1;
        threefry2x32(0u, key1, 0u, flat, o0, o1);
        unsigned bits = o0 ^ o1;
        float u = __uint_as_float((bits >> 9) | 0x3f800000u) - 1.f;
        y[cc] = (u < 0.8f) ? (y[cc] / 0.8f) : 0.f;
    }
    float4 o4; o4.x = y[0]; o4.y = y[1]; o4.z = y[2]; o4.w = y[3];
    ((float4*)(o_base + (size_t)w * CDIM))[lane] = o4;
}

// ---------------------------------------------------------------------------
// Host launcher — 11 launches; gemm_pair(rel0) at index 3 for ncu capture
// ---------------------------------------------------------------------------
extern "C" void kernel_launch(void* const* d_in, const int* in_sizes, int n_in,
                              void* d_out, int out_size)
{
    const float* x_met = (const float*)d_in[0];
    const float* x_rxn = (const float*)d_in[1];
    const int* ei_sub = (const int*)d_in[2];
    const int* ei_prod = (const int*)d_in[3];
    const int* ei_shared = (const int*)d_in[4];
    int n_met = in_sizes[0] / CDIM;
    int n_rxn = in_sizes[1] / CDIM;
    int E_sub = in_sizes[2] / 2;
    int E_prod = in_sizes[3] / 2;
    int E_shared = in_sizes[4] / 2;
    float* out = (float*)d_out;

    // relation order: 0=sub(met->rxn), 1=shared(rxn->rxn,+loops), 2=prod(rxn->met)
    const float* xs[3] = { x_met, x_rxn, x_rxn };
    const float* xd[3] = { x_rxn, x_rxn, x_met };
    int n_src[3] = { n_met, n_rxn, n_rxn };
    int n_dst[3] = { n_rxn, n_rxn, n_met };
    int baseidx[3] = { 5, 17, 11 };

    CsrArgs ca;
    ca.ei[0] = ei_sub;    ca.E[0] = E_sub;    ca.n_extra[0] = 0;     ca.n_dst[0] = n_rxn;
    ca.ei[1] = ei_shared; ca.E[1] = E_shared; ca.n_extra[1] = n_rxn; ca.n_dst[1] = n_rxn;
    ca.ei[2] = ei_prod;   ca.E[2] = E_prod;   ca.n_extra[2] = 0;     ca.n_dst[2] = n_met;

    int nmax_nodes = (n_rxn > n_met) ? n_rxn : n_met;
    int tot_max = 0;
    for (int r = 0; r < 3; r++) {
        int t = ca.E[r] + ca.n_extra[r];
        if (t > tot_max) tot_max = t;
    }

    // 0-2: CSR front half
    zero_all_kernel<<<(nmax_nodes + 255) / 256, 256>>>(ca.n_dst[0], ca.n_dst[1], ca.n_dst[2]);
    {
        dim3 g((tot_max + 255) / 256, 3);
        hist_all_kernel<<<g, 256>>>(ca);
    }
    scan_all_kernel<<<3, 1024>>>(ca.n_dst[0], ca.n_dst[1], ca.n_dst[2]);

    // 3: gemm_pair rel0 (ncu-captured launch)
    {
        int mmax = (n_src[0] > n_dst[0]) ? n_src[0] : n_dst[0];
        dim3 g((mmax + GBM - 1) / GBM, 4, 2);
        gemm_pair_kernel<<<g, 256>>>(xs[0], (const float*)d_in[baseidx[0] + 0],
                                     (const float*)d_in[baseidx[0] + 3], n_src[0],
                                     xd[0], (const float*)d_in[baseidx[0] + 1],
                                     (const float*)d_in[baseidx[0] + 4], n_dst[0]);
    }

    // 4: scatter (completes CSR)
    {
        dim3 g((tot_max + 255) / 256, 3);
        scatter_all_kernel<<<g, 256>>>(ca);
    }

    // 5: edge rel0
    edge_kernel<<<(n_dst[0] + 7) / 8, 256>>>(
        (const float*)d_in[baseidx[0] + 2], (const float*)d_in[baseidx[0] + 5],
        0, n_dst[0]);

    // 6-9: relations 1 and 2
    for (int r = 1; r < 3; r++) {
        int mmax = (n_src[r] > n_dst[r]) ? n_src[r] : n_dst[r];
        dim3 g((mmax + GBM - 1) / GBM, 4, 2);
        gemm_pair_kernel<<<g, 256>>>(xs[r], (const float*)d_in[baseidx[r] + 0],
                                     (const float*)d_in[baseidx[r] + 3], n_src[r],
                                     xd[r], (const float*)d_in[baseidx[r] + 1],
                                     (const float*)d_in[baseidx[r] + 4], n_dst[r]);
        edge_kernel<<<(n_dst[r] + 7) / 8, 256>>>(
            (const float*)d_in[baseidx[r] + 2], (const float*)d_in[baseidx[r] + 5],
            r, n_dst[r]);
    }

    // 10: fused finalize
    {
        int tw = n_rxn + n_met;
        finalize_all_kernel<<<(tw + 7) / 8, 256>>>(
            x_rxn, x_met,
            (const float*)d_in[23], (const float*)d_in[24],
            (const float*)d_in[25], (const float*)d_in[26],
            out, n_rxn, n_met);
    }
}